// round 17
// baseline (speedup 1.0000x reference)
#include <cuda_runtime.h>
#include <cuda_bf16.h>

// Problem: x [64,224,224,32] f32; W_cls [32,4]; b_cls [4].
// out[b] = rot90(x[b], k[b]) with k[b] = argmax(mean_hw(x[b]) @ W + b).
//
// R17 = resubmission of R16 (prior round was an infra container failure;
// deadlock audit in notes: prefetch hold-and-wait chains strictly decrease
// batch index by >DLY and terminate at the head groups, which are held only
// by non-blocking reduce tasks).
//
// R15 winner (persistent fused kernel, block task queue, 1024-px tasks,
// DLY=24 interleave, grid 1184, 4-wide front-batched gather) with the
// per-task synchronization stripped down:
//  - double-buffered task fetch: ONE __syncthreads per task
//  - warp-0-only cross-warp combine + done-count + in-warp argmax
//  - per-warp flag wait + shfl in the rotate path

#define BATCH 64
#define HW    224
#define PIX   (HW * HW)        // 50176
#define CH    32
#define NCHUNK 49
#define DLY   24
#define NGROUP (2 * BATCH)                    // 128
#define TOTAL_TASKS (NGROUP * NCHUNK)         // 6272
#define GRID_BLOCKS (148 * 8)                 // 1184

// Queue state: zero-init at load, restored by last exiting block.
__device__ float4   g_partial[BATCH * NCHUNK * 8];
__device__ int      g_k[BATCH];
__device__ unsigned g_ctr;
__device__ int      g_done[BATCH];
__device__ int      g_flag[BATCH];
__device__ unsigned g_exit;

// Gather affine coefficients (float4 units, before +q):
//   k=0: si=i,     sj=j      k=1: si=j,     sj=223-i
//   k=2: si=223-i, sj=223-j  k=3: si=223-j, sj=i
__constant__ int c_A[4] = { HW*8,      -8,      -HW*8,   8      };
__constant__ int c_B[4] = { 8,          HW*8,   -8,      -HW*8  };
__constant__ int c_C[4] = { 0,          223*8,  (223*HW+223)*8, 223*HW*8 };

__global__ void __launch_bounds__(256, 8) fused_kernel(const float4* __restrict__ x,
                                                       const float*  __restrict__ W_cls,
                                                       const float*  __restrict__ b_cls,
                                                       float4*       __restrict__ out) {
    __shared__ float4 sm[8][8];
    __shared__ int    sh_task[2];

    const int t    = threadIdx.x;
    const int lane = t & 31;
    const int warp = t >> 5;
    const int q    = t & 7;
    const unsigned FULL = 0xffffffffu;

    if (t == 0) sh_task[0] = (int)atomicAdd(&g_ctr, 1u);
    __syncthreads();

    for (int buf = 0;; buf ^= 1) {
        const int task = sh_task[buf];
        if (task >= TOTAL_TASKS) break;
        if (t == 0) sh_task[buf ^ 1] = (int)atomicAdd(&g_ctr, 1u);  // prefetch

        // -------- decode interleaved schedule (delay = DLY groups) --------
        const int g     = task / NCHUNK;
        const int slice = task - g * NCHUNK;
        int is_reduce, b;
        if (g < DLY)                 { is_reduce = 1; b = g; }
        else if (g < NGROUP - DLY)   { int h = g - DLY;
                                       is_reduce = !(h & 1);
                                       b = is_reduce ? (DLY + (h >> 1)) : (h >> 1); }
        else                         { is_reduce = 0;
                                       b = (BATCH - DLY) + (g - (NGROUP - DLY)); }

        if (is_reduce) {
            // ---------------- reduction chunk (order-identical to R1) -------
            const unsigned base = ((unsigned)b * PIX + (unsigned)slice * 1024u) * 8u;

            float4 s = make_float4(0.f, 0.f, 0.f, 0.f);
#pragma unroll 4
            for (int it = 0; it < 32; ++it) {
                unsigned pix = (unsigned)(it * 32 + (t >> 3));
                float4 v = __ldg(&x[base + pix * 8u + q]);
                s.x += v.x; s.y += v.y; s.z += v.z; s.w += v.w;
            }
#pragma unroll
            for (int off = 8; off <= 16; off <<= 1) {
                s.x += __shfl_xor_sync(FULL, s.x, off);
                s.y += __shfl_xor_sync(FULL, s.y, off);
                s.z += __shfl_xor_sync(FULL, s.z, off);
                s.w += __shfl_xor_sync(FULL, s.w, off);
            }
            if (lane < 8) sm[warp][lane] = s;
            __syncthreads();

            // Warp 0 does everything else; warps 1-7 fall through to the
            // end-of-iter barrier.
            if (warp == 0) {
                if (lane < 8) {
                    float4 acc = sm[0][lane];
#pragma unroll
                    for (int w = 1; w < 8; ++w) {
                        float4 v = sm[w][lane];
                        acc.x += v.x; acc.y += v.y; acc.z += v.z; acc.w += v.w;
                    }
                    g_partial[(b * NCHUNK + slice) * 8 + lane] = acc;
                    __threadfence();           // release before done-count
                }
                __syncwarp(FULL);

                int is_last = 0;
                if (lane == 0)
                    is_last = (atomicAdd(&g_done[b], 1) == NCHUNK - 1);
                is_last = __shfl_sync(FULL, is_last, 0);

                if (is_last) {
                    __threadfence();           // acquire others' partials
                    // lane = channel c; sum partials, then in-warp logits
                    const int qq = lane >> 2, r = lane & 3;
                    float ssum = 0.f;
                    for (int ch = 0; ch < NCHUNK; ++ch) {
                        float4 v = g_partial[(b * NCHUNK + ch) * 8 + qq];
                        ssum += (r == 0) ? v.x : (r == 1) ? v.y : (r == 2) ? v.z : v.w;
                    }
                    const float mean = ssum * (1.0f / (float)PIX);
                    float4 w4 = __ldg(&((const float4*)W_cls)[lane]);  // W[c][:]
                    float l0 = mean * w4.x, l1 = mean * w4.y,
                          l2 = mean * w4.z, l3 = mean * w4.w;
#pragma unroll
                    for (int off = 16; off >= 1; off >>= 1) {
                        l0 += __shfl_xor_sync(FULL, l0, off);
                        l1 += __shfl_xor_sync(FULL, l1, off);
                        l2 += __shfl_xor_sync(FULL, l2, off);
                        l3 += __shfl_xor_sync(FULL, l3, off);
                    }
                    if (lane == 0) {
                        l0 += __ldg(&b_cls[0]); l1 += __ldg(&b_cls[1]);
                        l2 += __ldg(&b_cls[2]); l3 += __ldg(&b_cls[3]);
                        float best = l0; int bi = 0;        // first-max
                        if (l1 > best) { best = l1; bi = 1; }
                        if (l2 > best) { best = l2; bi = 2; }
                        if (l3 > best) { best = l3; bi = 3; }
                        g_k[b] = bi;
                        __threadfence();
                        atomicExch(&g_flag[b], 1);
                    }
                }
            }
        } else {
            // -------- rotation slice: per-warp wait, 4-wide gather ---------
            int k;
            if (lane == 0) {
                while (0 == *(volatile int*)&g_flag[b]) __nanosleep(100);
                __threadfence();
                k = g_k[b];
            }
            k = __shfl_sync(FULL, k, 0);
            const int A = c_A[k], Bc = c_B[k];

            const float4* src_base = x   + (unsigned)b * PIX * 8u;
            float4*       out_base = out + (unsigned)b * PIX * 8u;

            int pix0 = slice * 1024 + (t >> 3);
            int i = pix0 / HW;
            int j = pix0 - i * HW;
            int soff = A * i + Bc * j + c_C[k] + q;   // src float4 offset
            int doff = pix0 * 8 + q;                  // dst float4 offset
            const int stepB   = 32 * Bc;
            const int wrapAdj = A - HW * Bc;

#pragma unroll
            for (int su = 0; su < 8; ++su) {
                int o0 = soff;
                j += 32; soff += stepB; if (j >= HW) { j -= HW; soff += wrapAdj; }
                int o1 = soff;
                j += 32; soff += stepB; if (j >= HW) { j -= HW; soff += wrapAdj; }
                int o2 = soff;
                j += 32; soff += stepB; if (j >= HW) { j -= HW; soff += wrapAdj; }
                int o3 = soff;
                j += 32; soff += stepB; if (j >= HW) { j -= HW; soff += wrapAdj; }
                float4 v0 = __ldg(&src_base[o0]);
                float4 v1 = __ldg(&src_base[o1]);
                float4 v2 = __ldg(&src_base[o2]);
                float4 v3 = __ldg(&src_base[o3]);
                __stcs(&out_base[doff        ], v0);
                __stcs(&out_base[doff +  256 ], v1);
                __stcs(&out_base[doff +  512 ], v2);
                __stcs(&out_base[doff +  768 ], v3);
                doff += 1024;
            }
        }

        __syncthreads();   // orders prefetch write + smem reuse; 1 per task
    }

    // ---- self-reset for next graph replay: last block out cleans up ------
    if (t == 0) {
        unsigned me = atomicAdd(&g_exit, 1u);
        if (me == GRID_BLOCKS - 1) {
            for (int i = 0; i < BATCH; ++i) { g_done[i] = 0; g_flag[i] = 0; }
            g_ctr  = 0u;
            g_exit = 0u;
            __threadfence();
        }
    }
}

extern "C" void kernel_launch(void* const* d_in, const int* in_sizes, int n_in,
                              void* d_out, int out_size) {
    const float4* x     = (const float4*)d_in[0];
    const float*  W_cls = (const float*)d_in[1];
    const float*  b_cls = (const float*)d_in[2];
    float4*       out   = (float4*)d_out;

    fused_kernel<<<GRID_BLOCKS, 256>>>(x, W_cls, b_cls, out);
}